// round 3
// baseline (speedup 1.0000x reference)
#include <cuda_runtime.h>
#include <math.h>

// signal (32, 1024, 2) f32 interleaved. Per (batch, channel):
//   anded[t] = -|s| - log1p(exp(-2e5|s|))/1e5
//   out[t]   = suffix max of anded  (EV_SCALE=1e9 maxish == hard max to ~1e-9)
//
// grid=32 (one CTA per batch), 256 threads, 4 timesteps/thread.
// Loads: 2x LDG.128 per thread (8 floats = 4 timesteps x 2 channels).
// Scan:  3 serial fmax -> 5-shfl warp suffix scan -> 1 barrier (8 warps)
//        -> 3-shfl scan of 8 warp totals -> combine -> 2x STG.128.

static constexpr int T = 1024;
static constexpr int B = 32;
static constexpr int THREADS = 256;
static constexpr int ELEMS = 4;          // timesteps per thread

__device__ __forceinline__ float anded_of(float c) {
    float a = fabsf(c);
    // expf underflows to 0 for a > ~4.4e-4 -> exactly -|c|; branch-free stable
    return -a - log1pf(expf(-200000.0f * a)) * 1e-5f;
}

__global__ __launch_bounds__(THREADS)
void suffix_robustness_kernel(const float4* __restrict__ signal,
                              float4* __restrict__ out) {
    __shared__ float totx[8];
    __shared__ float toty[8];

    const int b    = blockIdx.x;
    const int t    = threadIdx.x;        // thread handles timesteps 4t..4t+3
    const int lane = t & 31;
    const int wid  = t >> 5;

    // signal row b: 2048 floats = 512 float4. Thread t takes float4 idx 2t, 2t+1.
    const float4* row = signal + b * (T * 2 / 4);
    float4 p0 = row[2 * t];              // ts 4t:   (x0,y0,x1,y1)
    float4 p1 = row[2 * t + 1];          // ts 4t+2: (x2,y2,x3,y3)

    float ax0 = anded_of(p0.x), ay0 = anded_of(p0.y);
    float ax1 = anded_of(p0.z), ay1 = anded_of(p0.w);
    float ax2 = anded_of(p1.x), ay2 = anded_of(p1.y);
    float ax3 = anded_of(p1.z), ay3 = anded_of(p1.w);

    // Per-thread suffix max (in place): a_i = max(a_i .. a_3)
    ax2 = fmaxf(ax2, ax3);  ay2 = fmaxf(ay2, ay3);
    ax1 = fmaxf(ax1, ax2);  ay1 = fmaxf(ay1, ay2);
    ax0 = fmaxf(ax0, ax1);  ay0 = fmaxf(ay0, ay1);

    // Warp suffix-inclusive scan of thread totals (ax0/ay0).
    // shfl_down past lane 31 returns own value == identity for max.
    float sx = ax0, sy = ay0;
    #pragma unroll
    for (int off = 1; off < 32; off <<= 1) {
        float ox = __shfl_down_sync(0xffffffffu, sx, off);
        float oy = __shfl_down_sync(0xffffffffu, sy, off);
        sx = fmaxf(sx, ox);
        sy = fmaxf(sy, oy);
    }
    // Carry from later threads in this warp = scan value at lane+1.
    float cwx = __shfl_down_sync(0xffffffffu, sx, 1);
    float cwy = __shfl_down_sync(0xffffffffu, sy, 1);
    if (lane == 31) { cwx = -INFINITY; cwy = -INFINITY; }

    // Publish warp totals (scan value at lane 0).
    if (lane == 0) { totx[wid] = sx; toty[wid] = sy; }
    __syncthreads();

    // Every warp redundantly suffix-scans the 8 warp totals.
    float tx = (lane < 8) ? totx[lane] : -INFINITY;
    float ty = (lane < 8) ? toty[lane] : -INFINITY;
    #pragma unroll
    for (int off = 1; off < 8; off <<= 1) {
        float ox = __shfl_down_sync(0xffffffffu, tx, off);
        float oy = __shfl_down_sync(0xffffffffu, ty, off);
        tx = fmaxf(tx, ox);
        ty = fmaxf(ty, oy);
    }
    // Carry from later warps = scanned total at lane wid+1 (wid 7 -> -inf).
    float cbx = __shfl_sync(0xffffffffu, tx, wid + 1);
    float cby = __shfl_sync(0xffffffffu, ty, wid + 1);
    if (wid == 7) { cbx = -INFINITY; cby = -INFINITY; }

    float cx = fmaxf(cwx, cbx);          // total carry from all later elements
    float cy = fmaxf(cwy, cby);

    float4 ox4, oy4;
    ox4.x = fmaxf(ax0, cx);  oy4.x = fmaxf(ay0, cy);
    ox4.y = fmaxf(ax1, cx);  oy4.y = fmaxf(ay1, cy);
    ox4.z = fmaxf(ax2, cx);  oy4.z = fmaxf(ay2, cy);
    ox4.w = fmaxf(ax3, cx);  oy4.w = fmaxf(ay3, cy);

    // Outputs: (final, final_2) concatenated, each (32,1024) row-major.
    // Row b occupies 256 float4; thread t writes float4 index t.
    out[b * (T / 4) + t]                 = ox4;
    out[B * (T / 4) + b * (T / 4) + t]   = oy4;
}

extern "C" void kernel_launch(void* const* d_in, const int* in_sizes, int n_in,
                              void* d_out, int out_size) {
    const float4* signal = (const float4*)d_in[0];
    float4* out = (float4*)d_out;
    suffix_robustness_kernel<<<B, THREADS>>>(signal, out);
}

// round 4
// speedup vs baseline: 1.0725x; 1.0725x over previous
#include <cuda_runtime.h>
#include <math.h>

// signal (32, 1024, 2) f32 interleaved. Per (batch, channel):
//   anded[t] = -|s| - log1p(exp(-2e5|s|))/1e5
//   out[t]   = suffix max of anded  (EV_SCALE=1e9 maxish == hard max to ~1e-9)
//
// grid=32 (one CTA per batch), 256 threads, 4 timesteps/thread.
// Fast-intrinsic math: __logf(1+__expf(-2e5 a))*1e-5 — abs err ~1e-11 on a
// correction bounded by 6.9e-6; negligible vs 1e-3 tolerance (measured 7e-8).
// Scan: 3 serial fmax -> 5-shfl warp suffix scan -> 1 barrier (8 warps)
//       -> 3-shfl scan of 8 warp totals -> combine -> 2x STG.128.

static constexpr int T = 1024;
static constexpr int B = 32;
static constexpr int THREADS = 256;

__device__ __forceinline__ float anded_of(float c) {
    float a = fabsf(c);
    // MUFU EX2/LG2 path: ~6 SASS instrs vs ~25 for expf+log1pf.
    return -a - __logf(1.0f + __expf(-200000.0f * a)) * 1e-5f;
}

__global__ __launch_bounds__(THREADS)
void suffix_robustness_kernel(const float4* __restrict__ signal,
                              float4* __restrict__ out) {
    __shared__ float totx[8];
    __shared__ float toty[8];

    const int b    = blockIdx.x;
    const int t    = threadIdx.x;        // thread handles timesteps 4t..4t+3
    const int lane = t & 31;
    const int wid  = t >> 5;

    // signal row b: 2048 floats = 512 float4. Thread t takes float4 idx 2t, 2t+1.
    const float4* row = signal + b * (T * 2 / 4);
    float4 p0 = row[2 * t];              // ts 4t:   (x0,y0,x1,y1)
    float4 p1 = row[2 * t + 1];          // ts 4t+2: (x2,y2,x3,y3)

    float ax0 = anded_of(p0.x), ay0 = anded_of(p0.y);
    float ax1 = anded_of(p0.z), ay1 = anded_of(p0.w);
    float ax2 = anded_of(p1.x), ay2 = anded_of(p1.y);
    float ax3 = anded_of(p1.z), ay3 = anded_of(p1.w);

    // Per-thread suffix max (in place): a_i = max(a_i .. a_3)
    ax2 = fmaxf(ax2, ax3);  ay2 = fmaxf(ay2, ay3);
    ax1 = fmaxf(ax1, ax2);  ay1 = fmaxf(ay1, ay2);
    ax0 = fmaxf(ax0, ax1);  ay0 = fmaxf(ay0, ay1);

    // Warp suffix-inclusive scan of thread totals (ax0/ay0).
    // shfl_down past lane 31 returns own value == identity for max.
    float sx = ax0, sy = ay0;
    #pragma unroll
    for (int off = 1; off < 32; off <<= 1) {
        float ox = __shfl_down_sync(0xffffffffu, sx, off);
        float oy = __shfl_down_sync(0xffffffffu, sy, off);
        sx = fmaxf(sx, ox);
        sy = fmaxf(sy, oy);
    }
    // Carry from later threads in this warp = scan value at lane+1.
    float cwx = __shfl_down_sync(0xffffffffu, sx, 1);
    float cwy = __shfl_down_sync(0xffffffffu, sy, 1);
    if (lane == 31) { cwx = -INFINITY; cwy = -INFINITY; }

    // Publish warp totals (scan value at lane 0).
    if (lane == 0) { totx[wid] = sx; toty[wid] = sy; }
    __syncthreads();

    // Every warp redundantly suffix-scans the 8 warp totals.
    float tx = (lane < 8) ? totx[lane] : -INFINITY;
    float ty = (lane < 8) ? toty[lane] : -INFINITY;
    #pragma unroll
    for (int off = 1; off < 8; off <<= 1) {
        float ox = __shfl_down_sync(0xffffffffu, tx, off);
        float oy = __shfl_down_sync(0xffffffffu, ty, off);
        tx = fmaxf(tx, ox);
        ty = fmaxf(ty, oy);
    }
    // Carry from later warps = scanned total at lane wid+1 (wid 7 -> -inf).
    float cbx = __shfl_sync(0xffffffffu, tx, wid + 1);
    float cby = __shfl_sync(0xffffffffu, ty, wid + 1);
    if (wid == 7) { cbx = -INFINITY; cby = -INFINITY; }

    float cx = fmaxf(cwx, cbx);          // total carry from all later elements
    float cy = fmaxf(cwy, cby);

    float4 ox4, oy4;
    ox4.x = fmaxf(ax0, cx);  oy4.x = fmaxf(ay0, cy);
    ox4.y = fmaxf(ax1, cx);  oy4.y = fmaxf(ay1, cy);
    ox4.z = fmaxf(ax2, cx);  oy4.z = fmaxf(ay2, cy);
    ox4.w = fmaxf(ax3, cx);  oy4.w = fmaxf(ay3, cy);

    // Outputs: (final, final_2) concatenated, each (32,1024) row-major.
    out[b * (T / 4) + t]                 = ox4;
    out[B * (T / 4) + b * (T / 4) + t]   = oy4;
}

extern "C" void kernel_launch(void* const* d_in, const int* in_sizes, int n_in,
                              void* d_out, int out_size) {
    const float4* signal = (const float4*)d_in[0];
    float4* out = (float4*)d_out;
    suffix_robustness_kernel<<<B, THREADS>>>(signal, out);
}